// round 14
// baseline (speedup 1.0000x reference)
#include <cuda_runtime.h>
#include <math.h>

// ---------------------------------------------------------------------------
// GemoLoss — GB300. n=4, h=768, w=1024, S=131072.
// R13: persistent fused prep kernel (edge/theta live in SMEM, two device-side
//      grid syncs, masks packed in registers) + floor-level k_sample.
// ---------------------------------------------------------------------------

#define NIMG 4
#define H    768
#define W    1024
#define P    (H * W)          // 786432
#define S    131072
#define NB   (P / 1024)       // 768 tiles (rows) per image
#define TILES (NIMG * NB)     // 3072

#define PBLOCKS 296           // 2 blocks/SM on >=148 SMs -> all resident
#define TMAX    11            // ceil(TILES / PBLOCKS)

#define MASK_VALUE (-1e-8f)

// ------------- device scratch (zero-initialized at module load) -------------
__device__ float2   g_pt   [NIMG * P];   // packed (inp, tgt) per pixel
__device__ int2     g_epack[NIMG * P];   // packed (pixel, theta_bits)
__device__ int      g_vsel [NIMG * P];   // stable select for valid mask
__device__ unsigned g_emax_bits[NIMG];   // edge max as float bits
__device__ int      g_eblk[TILES];       // per-tile e counts
__device__ int      g_vblk[TILES];       // per-tile v counts
__device__ int      g_ecount[NIMG];
__device__ int      g_vcount[NIMG];
__device__ int      g_barrier[2];        // grid-sync counters
__device__ double   g_acc_eq;
__device__ double   g_acc_uq;

// ----------------------------------------------------------------------------
__device__ __forceinline__ void grid_sync(int phase, int tid) {
    __syncthreads();
    __threadfence();
    if (tid == 0) {
        atomicAdd(&g_barrier[phase], 1);
        while (atomicAdd(&g_barrier[phase], 0) < PBLOCKS)
            __nanosleep(64);
    }
    __syncthreads();
}

// ----------------------------------------------------------------------------
// Sobel core: 4 consecutive pixels of row y. Cross-correlation (lax.conv does
// not flip kernels). Border rows/cols -> 0.
__device__ __forceinline__ void sobel4(const float* __restrict__ I,
                                       int y, int x0,
                                       float e[4], float gxo[4], float gyo[4]) {
    e[0] = e[1] = e[2] = e[3] = 0.f;
    gxo[0] = gxo[1] = gxo[2] = gxo[3] = 0.f;
    gyo[0] = gyo[1] = gyo[2] = gyo[3] = 0.f;
    if (y <= 0 || y >= H - 1) return;

    float r0[6], r1[6], r2[6];
    float4 a0 = __ldg((const float4*)(I + (y - 1) * W + x0));
    float4 a1 = __ldg((const float4*)(I + (y    ) * W + x0));
    float4 a2 = __ldg((const float4*)(I + (y + 1) * W + x0));
    r0[1]=a0.x; r0[2]=a0.y; r0[3]=a0.z; r0[4]=a0.w;
    r1[1]=a1.x; r1[2]=a1.y; r1[3]=a1.z; r1[4]=a1.w;
    r2[1]=a2.x; r2[2]=a2.y; r2[3]=a2.z; r2[4]=a2.w;
    if (x0 > 0) {
        r0[0] = __ldg(I + (y - 1) * W + x0 - 1);
        r1[0] = __ldg(I + (y    ) * W + x0 - 1);
        r2[0] = __ldg(I + (y + 1) * W + x0 - 1);
    } else { r0[0] = r1[0] = r2[0] = 0.f; }
    if (x0 + 4 < W) {
        r0[5] = __ldg(I + (y - 1) * W + x0 + 4);
        r1[5] = __ldg(I + (y    ) * W + x0 + 4);
        r2[5] = __ldg(I + (y + 1) * W + x0 + 4);
    } else { r0[5] = r1[5] = r2[5] = 0.f; }

    #pragma unroll
    for (int j = 0; j < 4; j++) {
        int x = x0 + j;
        if (x > 0 && x < W - 1) {
            float a  = r0[j], b = r0[j + 1], c = r0[j + 2];
            float d  = r1[j],                f = r1[j + 2];
            float g  = r2[j], hh = r2[j + 1], i = r2[j + 2];
            // kx = [[-1,0,1],[-2,0,2],[-1,0,1]], ky = [[1,2,1],[0,0,0],[-1,-2,-1]]
            float gx = -a;  gx += c;  gx += -2.0f * d;  gx += 2.0f * f;  gx += -g;  gx += i;
            float gy =  a;  gy += 2.0f * b;  gy += c;  gy += -g;  gy += -2.0f * hh; gy += -i;
            e[j]   = sqrtf(gx * gx + gy * gy);
            gxo[j] = gx;
            gyo[j] = gy;
        }
    }
}

// ----------------------------------------------------------------------------
// Persistent fused prep: sobel + pt pack + masks + counts + stable scatter,
// with edge/theta resident in SMEM across the three phases.
__global__ void __launch_bounds__(256, 2)
k_prep(const float* __restrict__ images,
       const float* __restrict__ inp,
       const float* __restrict__ tgt) {
    extern __shared__ char smem_raw[];
    float* theta_s = (float*)smem_raw;             // TMAX*1024 floats
    float* edge_s  = theta_s + TMAX * 1024;        // TMAX*1024 floats

    int tid  = threadIdx.x;
    int bid  = blockIdx.x;
    int lane = tid & 31, wid = tid >> 5;
    int x0   = tid * 4;
    const unsigned full = 0xffffffffu;

    __shared__ float smax[8];
    __shared__ int   sct[8];
    __shared__ int   wce[8], wcv[8], woe[8], wov[8];
    __shared__ int   wbe[8], wbv[8];
    __shared__ int   s_offe, s_offv, s_tote, s_totv;

    unsigned long long packed_ne = 0ull;
    unsigned long long packed_nv = 0ull;

    // ================= phase 1: sobel -> smem, pt pack, v bits ==============
    {
        int v = 0;
        for (int tile = bid; tile < TILES; tile += PBLOCKS, v++) {
            int img = tile / NB;
            int y   = tile - img * NB;          // 1 tile == 1 row

            // (inp,tgt) pack + v nibble
            int g4 = tile * 256 + tid;
            float4 tv = __ldg((const float4*)(tgt) + g4);
            float4 iv = __ldg((const float4*)(inp) + g4);
            float4* pt4 = (float4*)g_pt;
            pt4[g4 * 2    ] = make_float4(iv.x, tv.x, iv.y, tv.y);
            pt4[g4 * 2 + 1] = make_float4(iv.z, tv.z, iv.w, tv.w);
            unsigned nv = (unsigned)(tv.x > MASK_VALUE)
                        | ((unsigned)(tv.y > MASK_VALUE) << 1)
                        | ((unsigned)(tv.z > MASK_VALUE) << 2)
                        | ((unsigned)(tv.w > MASK_VALUE) << 3);
            packed_nv |= (unsigned long long)nv << (4 * v);

            // sobel + theta
            float e[4], gx[4], gy[4];
            sobel4(images + (size_t)img * 3 * P, y, x0, e, gx, gy);
            float th[4];
            #pragma unroll
            for (int j = 0; j < 4; j++) {
                int x = x0 + j;
                th[j] = (y > 0 && y < H - 1 && x > 0 && x < W - 1)
                        ? atan2f(gy[j], gx[j]) : 0.0f;
            }
            *(float4*)&edge_s [v * 1024 + x0] = make_float4(e[0], e[1], e[2], e[3]);
            *(float4*)&theta_s[v * 1024 + x0] = make_float4(th[0], th[1], th[2], th[3]);

            // block reductions: edge max + v count
            float m = fmaxf(fmaxf(e[0], e[1]), fmaxf(e[2], e[3]));
            int cv = __popc(nv);
            #pragma unroll
            for (int off = 16; off; off >>= 1) {
                m  = fmaxf(m, __shfl_down_sync(full, m, off));
                cv += __shfl_down_sync(full, cv, off);
            }
            if (lane == 0) { smax[wid] = m; sct[wid] = cv; }
            __syncthreads();
            if (tid == 0) {
                float mm = smax[0]; int tvc = sct[0];
                #pragma unroll
                for (int i = 1; i < 8; i++) { mm = fmaxf(mm, smax[i]); tvc += sct[i]; }
                g_vblk[tile] = tvc;
                atomicAdd(&g_vcount[img], tvc);
                atomicMax(&g_emax_bits[img], __float_as_uint(mm));
            }
            __syncthreads();
        }
    }
    grid_sync(0, tid);

    // ================= phase 2: e-mask bits + per-tile counts ===============
    {
        int v = 0;
        for (int tile = bid; tile < TILES; tile += PBLOCKS, v++) {
            int img = tile / NB;
            float thresh = 0.1f * __uint_as_float(__ldcg(&g_emax_bits[img]));
            float4 ed = *(float4*)&edge_s[v * 1024 + x0];
            unsigned ne = (unsigned)(ed.x >= thresh)
                        | ((unsigned)(ed.y >= thresh) << 1)
                        | ((unsigned)(ed.z >= thresh) << 2)
                        | ((unsigned)(ed.w >= thresh) << 3);
            packed_ne |= (unsigned long long)ne << (4 * v);

            int ce = __popc(ne);
            #pragma unroll
            for (int off = 16; off; off >>= 1)
                ce += __shfl_down_sync(full, ce, off);
            if (lane == 0) sct[wid] = ce;
            __syncthreads();
            if (tid == 0) {
                int te = 0;
                #pragma unroll
                for (int i = 0; i < 8; i++) te += sct[i];
                g_eblk[tile] = te;
                atomicAdd(&g_ecount[img], te);
            }
            __syncthreads();
        }
    }
    grid_sync(1, tid);

    // ================= phase 3: stable scatter (edge smem now dead) =========
    {
        int2* s_e = (int2*)edge_s;                 // 1024 int2 = 8KB
        int*  s_v = (int*)(edge_s + 2048);         // next 4KB
        int v = 0;
        for (int tile = bid; tile < TILES; tile += PBLOCKS, v++) {
            int img = tile / NB;
            int b   = tile - img * NB;
            bool vall = (__ldcg(&g_vcount[img]) == P);

            unsigned ne = (unsigned)(packed_ne >> (4 * v)) & 0xFu;
            unsigned nv = vall ? 0u : ((unsigned)(packed_nv >> (4 * v)) & 0xFu);
            int ce = __popc(ne);
            int cv = __popc(nv);

            // offsets: sum of preceding tile counts of same image
            int oe = 0, ov = 0;
            for (int t2 = tid; t2 < b; t2 += 256) {
                oe += __ldcg(&g_eblk[img * NB + t2]);
                if (!vall) ov += __ldcg(&g_vblk[img * NB + t2]);
            }

            // warp: inclusive scan of (ce,cv), reduce of (oe,ov)
            int ice = ce, icv = cv;
            #pragma unroll
            for (int off = 1; off < 32; off <<= 1) {
                int a = __shfl_up_sync(full, ice, off);
                int c = __shfl_up_sync(full, icv, off);
                if (lane >= off) { ice += a; icv += c; }
            }
            #pragma unroll
            for (int off = 16; off; off >>= 1) {
                oe += __shfl_down_sync(full, oe, off);
                ov += __shfl_down_sync(full, ov, off);
            }

            if (lane == 31) { wce[wid] = ice; wcv[wid] = icv; }
            if (lane == 0)  { woe[wid] = oe;  wov[wid] = ov;  }
            __syncthreads();
            if (tid == 0) {
                int offE = 0, offV = 0;
                #pragma unroll
                for (int i = 0; i < 8; i++) { offE += woe[i]; offV += wov[i]; }
                int accE = 0, accV = 0;
                #pragma unroll
                for (int i = 0; i < 8; i++) {
                    wbe[i] = accE; accE += wce[i];
                    wbv[i] = accV; accV += wcv[i];
                }
                s_offe = offE; s_offv = offV;
                s_tote = accE; s_totv = accV;
            }
            __syncthreads();

            // compact into shared at stable local ranks
            float4 th4 = *(float4*)&theta_s[v * 1024 + x0];
            float thv[4] = { th4.x, th4.y, th4.z, th4.w };
            int le = wbe[wid] + (ice - ce);
            int p0 = b * 1024 + x0;
            #pragma unroll
            for (int j = 0; j < 4; j++)
                if ((ne >> j) & 1u)
                    s_e[le++] = make_int2(p0 + j, __float_as_int(thv[j]));
            if (!vall) {
                int lv = wbv[wid] + (icv - cv);
                #pragma unroll
                for (int j = 0; j < 4; j++)
                    if ((nv >> j) & 1u)
                        s_v[lv++] = p0 + j;
            }
            __syncthreads();

            // coalesced global stores
            size_t imgP = (size_t)img * P;
            int tote = s_tote, offe = s_offe;
            for (int t2 = tid; t2 < tote; t2 += 256)
                g_epack[imgP + offe + t2] = s_e[t2];
            if (!vall) {
                int totv = s_totv, offv = s_offv;
                for (int t2 = tid; t2 < totv; t2 += 256)
                    g_vsel[imgP + offv + t2] = s_v[t2];
            }
            __syncthreads();
        }
    }
}

// ----------------------------------------------------------------------------
// Main sampling kernel (at L1tex wavefront floor): one thread = four samples,
// both random phases batched 4-wide, sequential inputs as int4.
#define IPT 4
__global__ void __launch_bounds__(128)
k_sample(const int* __restrict__ ra,
         const int* __restrict__ rd,
         const int* __restrict__ rp) {
    int t = blockIdx.x * blockDim.x + threadIdx.x;   // < NIMG*S/IPT
    float eqf = 0.0f, uqf = 0.0f;

    {
        int img = t / (S / IPT);
        int g   = t - img * (S / IPT);               // sample group in image
        size_t imgP = (size_t)img * P;
        const float2* pt_i = g_pt + imgP;

        int ec = g_ecount[img];
        int vc = g_vcount[img];

        // ---- phase 0: vectorized sequential inputs ----
        int4 rav  = __ldg((const int4*)ra + img * (S / IPT) + g);
        int4 rdv[4];
        #pragma unroll
        for (int j = 0; j < 4; j++)
            rdv[j] = __ldg((const int4*)rd + (img * 4 + j) * (S / IPT) + g);
        int4 rpa = __ldg((const int4*)rp + img * (S / 2) + 2 * g);      // s0,s1
        int4 rpb = __ldg((const int4*)rp + img * (S / 2) + 2 * g + 1);  // s2,s3
        int rav_i[IPT] = { rav.x, rav.y, rav.z, rav.w };
        int rpA[IPT]   = { rpa.x, rpa.z, rpb.x, rpb.z };
        int rpB[IPT]   = { rpa.y, rpa.w, rpb.y, rpb.w };

        // ---- phase 1: 4 independent anchor gathers ----
        int2 ap[IPT];
        if (ec > 0) {
            #pragma unroll
            for (int i = 0; i < IPT; i++)
                ap[i] = __ldg(g_epack + imgP + (rav_i[i] % ec));
        } else {
            // no edge pixels: argsort identity -> anchor 0 (border => theta 0)
            int2 z = make_int2(0, __float_as_int(0.0f));
            #pragma unroll
            for (int i = 0; i < IPT; i++) ap[i] = z;
        }

        // ---- phase 2: trig + index computation (all samples) ----
        int q[IPT][6];
        #pragma unroll
        for (int i = 0; i < IPT; i++) {
            float th = __int_as_float(ap[i].y);
            float ct, st;
            sincosf(th, &st, &ct);
            int row_a = ap[i].x / W;
            int col_a = ap[i].x - row_a * W;
            int rdj[4] = { (&rdv[0].x)[i], (&rdv[1].x)[i], (&rdv[2].x)[i], (&rdv[3].x)[i] };
            #pragma unroll
            for (int j = 0; j < 4; j++) {
                float sign = (j < 2) ? -1.0f : 1.0f;
                float d    = ((float)rdj[j] + 2.0f) * sign;
                int cc = col_a + (int)rintf(d * ct);   // jnp.round = half-to-even
                int rr = row_a + (int)rintf(d * st);
                cc = min(max(cc, 0), W - 1);
                rr = min(max(rr, 0), H - 1);
                q[i][j] = rr * W + cc;
            }
        }
        if (vc == P) {                 // all-valid: vsel is identity
            #pragma unroll
            for (int i = 0; i < IPT; i++) {
                q[i][4] = rpA[i] % vc;
                q[i][5] = rpB[i] % vc;
            }
        } else if (vc > 0) {
            #pragma unroll
            for (int i = 0; i < IPT; i++) {
                q[i][4] = __ldg(g_vsel + imgP + (rpA[i] % vc));
                q[i][5] = __ldg(g_vsel + imgP + (rpB[i] % vc));
            }
        } else {
            #pragma unroll
            for (int i = 0; i < IPT; i++) { q[i][4] = 0; q[i][5] = 0; }
        }

        // ---- phase 3: 24 independent packed gathers ----
        float2 pv[IPT][6];
        #pragma unroll
        for (int i = 0; i < IPT; i++)
            #pragma unroll
            for (int j = 0; j < 6; j++)
                pv[i][j] = __ldg(pt_i + q[i][j]);

        // ---- phase 4: pair math ----
        const int PA[4] = {0, 1, 2, 4};
        const int PB[4] = {1, 2, 3, 5};
        const float hi = 1.0f + 0.03f;             // 1 + SIGMA in f32
        const float lo = (float)(1.0 / 1.03);      // double-computed like Python

        #pragma unroll
        for (int i = 0; i < IPT; i++) {
            #pragma unroll
            for (int k = 0; k < 4; k++) {
                float iA = pv[i][PA[k]].x, iB = pv[i][PB[k]].x;
                float tA = pv[i][PA[k]].y, tB = pv[i][PB[k]].y;

                float cm = ((tA > MASK_VALUE) && (tB > MASK_VALUE)) ? 1.0f : 0.0f;
                float ratio = (tA + 1e-6f) / (tB + 1e-6f);
                bool  meq = (ratio < hi) && (ratio > lo);

                if (meq) {
                    float dd = iA - iB;
                    eqf += dd * dd * cm;
                } else {
                    float lbl = (ratio >= hi) ? 1.0f : -1.0f;
                    uqf += log1pf(expf((iB - iA) * lbl)) * cm;
                }
            }
        }
    }

    // block reduce (promote to double) -> single atomicAdd pair per block
    double eq = (double)eqf, uq = (double)uqf;
    #pragma unroll
    for (int off = 16; off; off >>= 1) {
        eq += __shfl_down_sync(0xffffffffu, eq, off);
        uq += __shfl_down_sync(0xffffffffu, uq, off);
    }
    __shared__ double sh_eq[4];
    __shared__ double sh_uq[4];
    int lane = threadIdx.x & 31, wid = threadIdx.x >> 5;
    if (lane == 0) { sh_eq[wid] = eq; sh_uq[wid] = uq; }
    __syncthreads();
    if (wid == 0 && lane == 0) {
        eq = sh_eq[0] + sh_eq[1] + sh_eq[2] + sh_eq[3];
        uq = sh_uq[0] + sh_uq[1] + sh_uq[2] + sh_uq[3];
        atomicAdd(&g_acc_eq, eq);
        atomicAdd(&g_acc_uq, uq);
    }
}

// ----------------------------------------------------------------------------
// Final: compute loss, then reset all accumulators/counters/barriers so the
// next invocation (graph replay) starts from the same zero state.
__global__ void k_final(float* __restrict__ out) {
    int t = threadIdx.x;
    if (t == 0) {
        const double ALPHA = 1.0;
        double denom = 4.0 * (double)S;                   // pairs per image
        double loss  = (ALPHA * g_acc_eq + g_acc_uq) / denom / (double)NIMG;
        out[0] = (float)loss;
        g_acc_eq = 0.0;
        g_acc_uq = 0.0;
        g_barrier[0] = 0;
        g_barrier[1] = 0;
    }
    if (t < NIMG) {
        g_emax_bits[t] = 0u;
        g_ecount[t] = 0;
        g_vcount[t] = 0;
    }
}

// ----------------------------------------------------------------------------
extern "C" void kernel_launch(void* const* d_in, const int* in_sizes, int n_in,
                              void* d_out, int out_size) {
    (void)in_sizes; (void)n_in; (void)out_size;

    const float* inputs  = (const float*)d_in[0];
    const float* targets = (const float*)d_in[1];
    const float* images  = (const float*)d_in[2];
    const int*   ra      = (const int*)d_in[3];
    const int*   rd      = (const int*)d_in[4];
    const int*   rp      = (const int*)d_in[5];
    float*       out     = (float*)d_out;

    static int smem_set = 0;
    const int PREP_SMEM = TMAX * 1024 * 4 * 2;   // edge + theta, 90112 B
    if (!smem_set) {
        cudaFuncSetAttribute(k_prep, cudaFuncAttributeMaxDynamicSharedMemorySize,
                             PREP_SMEM);
        smem_set = 1;
    }

    k_prep  <<<PBLOCKS, 256, PREP_SMEM>>>(images, inputs, targets);
    k_sample<<<(NIMG * S / IPT) / 128, 128>>>(ra, rd, rp);
    k_final <<<1, 32>>>(out);
}

// round 15
// speedup vs baseline: 1.2788x; 1.2788x over previous
#include <cuda_runtime.h>
#include <math.h>

// ---------------------------------------------------------------------------
// GemoLoss — GB300. n=4, h=768, w=1024, S=131072.
// R14: R10 skeleton (proven fastest) + k_sample IPT=2 (2x thread count to
//      lift occupancy cap) + k_final folded into k_sample via ticket.
// ---------------------------------------------------------------------------

#define NIMG 4
#define H    768
#define W    1024
#define P    (H * W)          // 786432
#define S    131072
#define NB   (P / 1024)       // 768 tiles of 1024 pixels per image

#define MASK_VALUE (-1e-8f)

// ------------- device scratch (zero-initialized at module load) -------------
__device__ float    g_edge [NIMG * P];
__device__ float    g_theta[NIMG * P];
__device__ float2   g_pt   [NIMG * P];        // packed (inp, tgt) per pixel
__device__ int2     g_epack[NIMG * P];        // packed (pixel, theta_bits)
__device__ int      g_vsel [NIMG * P];        // stable select for valid mask
__device__ unsigned g_emaskw[NIMG * NB * 32]; // 1024-bit tile masks
__device__ unsigned g_vmaskw[NIMG * NB * 32];
__device__ unsigned g_emax_bits[NIMG];        // edge max as float bits
__device__ int      g_eblk[NIMG * NB];        // per-tile mask counts
__device__ int      g_vblk[NIMG * NB];
__device__ int      g_ecount[NIMG];
__device__ int      g_vcount[NIMG];
__device__ unsigned g_ticket;                 // last-block detection
__device__ double   g_acc_eq;
__device__ double   g_acc_uq;

// ----------------------------------------------------------------------------
// Sobel on channel 0 (cross-correlation). One block == one 1024-px tile,
// 4 consecutive pixels per thread. Border pixels get edge=0, theta=0.
// Fused: per-image edge max, (inp,tgt) packing, v-mask bits/counts.
__global__ void k_sobel(const float* __restrict__ images,
                        const float* __restrict__ inp,
                        const float* __restrict__ tgt) {
    int gid = blockIdx.x * blockDim.x + threadIdx.x;   // < NIMG*P/4
    int img = gid / (P / 4);
    int t   = gid - img * (P / 4);
    int p0  = t * 4;                                   // 4 px, same row (W%4==0)
    int y   = p0 / W;
    int x0  = p0 - y * W;
    int tid = threadIdx.x;
    int lane = tid & 31, wid = tid >> 5;
    const unsigned full = 0xffffffffu;

    // pack (inp,tgt) and build v-mask nibble from the same tgt load
    float4 tv = __ldg((const float4*)(tgt) + gid);
    {
        float4 iv = __ldg((const float4*)(inp) + gid);
        float4* pt4 = (float4*)g_pt;
        pt4[gid * 2    ] = make_float4(iv.x, tv.x, iv.y, tv.y);
        pt4[gid * 2 + 1] = make_float4(iv.z, tv.z, iv.w, tv.w);
    }
    unsigned nv = (unsigned)(tv.x > MASK_VALUE)
                | ((unsigned)(tv.y > MASK_VALUE) << 1)
                | ((unsigned)(tv.z > MASK_VALUE) << 2)
                | ((unsigned)(tv.w > MASK_VALUE) << 3);

    float e[4]  = {0.f, 0.f, 0.f, 0.f};
    float th[4] = {0.f, 0.f, 0.f, 0.f};
    if (y > 0 && y < H - 1) {
        const float* I = images + (size_t)img * 3 * P;
        float r0[6], r1[6], r2[6];
        float4 a0 = __ldg((const float4*)(I + (y - 1) * W + x0));
        float4 a1 = __ldg((const float4*)(I + (y    ) * W + x0));
        float4 a2 = __ldg((const float4*)(I + (y + 1) * W + x0));
        r0[1]=a0.x; r0[2]=a0.y; r0[3]=a0.z; r0[4]=a0.w;
        r1[1]=a1.x; r1[2]=a1.y; r1[3]=a1.z; r1[4]=a1.w;
        r2[1]=a2.x; r2[2]=a2.y; r2[3]=a2.z; r2[4]=a2.w;
        if (x0 > 0) {
            r0[0] = __ldg(I + (y - 1) * W + x0 - 1);
            r1[0] = __ldg(I + (y    ) * W + x0 - 1);
            r2[0] = __ldg(I + (y + 1) * W + x0 - 1);
        } else { r0[0] = r1[0] = r2[0] = 0.f; }
        if (x0 + 4 < W) {
            r0[5] = __ldg(I + (y - 1) * W + x0 + 4);
            r1[5] = __ldg(I + (y    ) * W + x0 + 4);
            r2[5] = __ldg(I + (y + 1) * W + x0 + 4);
        } else { r0[5] = r1[5] = r2[5] = 0.f; }

        #pragma unroll
        for (int j = 0; j < 4; j++) {
            int x = x0 + j;
            if (x > 0 && x < W - 1) {
                float a  = r0[j], b = r0[j + 1], c = r0[j + 2];
                float d  = r1[j],                f = r1[j + 2];
                float g  = r2[j], hh = r2[j + 1], i = r2[j + 2];
                // kx = [[-1,0,1],[-2,0,2],[-1,0,1]], ky = [[1,2,1],[0,0,0],[-1,-2,-1]]
                float gx = -a;  gx += c;  gx += -2.0f * d;  gx += 2.0f * f;  gx += -g;  gx += i;
                float gy =  a;  gy += 2.0f * b;  gy += c;  gy += -g;  gy += -2.0f * hh; gy += -i;
                e[j]  = sqrtf(gx * gx + gy * gy);
                th[j] = atan2f(gy, gx);
            }
        }
    }
    *(float4*)(g_edge  + (size_t)gid * 4) = make_float4(e[0],  e[1],  e[2],  e[3]);
    *(float4*)(g_theta + (size_t)gid * 4) = make_float4(th[0], th[1], th[2], th[3]);

    // v-mask word assembly (8 lanes * 4 bits) + tile count
    unsigned wv = nv << (4 * (lane & 7));
    #pragma unroll
    for (int off = 4; off; off >>= 1) wv |= __shfl_xor_sync(full, wv, off);
    if ((lane & 7) == 0)
        g_vmaskw[(size_t)blockIdx.x * 32 + (tid >> 3)] = wv;

    // block reductions: edge max + v count
    __shared__ float smax[8];
    __shared__ int   scv[8];
    float m = fmaxf(fmaxf(e[0], e[1]), fmaxf(e[2], e[3]));
    int cv = __popc(nv);
    #pragma unroll
    for (int off = 16; off; off >>= 1) {
        m  = fmaxf(m, __shfl_down_sync(full, m, off));
        cv += __shfl_down_sync(full, cv, off);
    }
    if (lane == 0) { smax[wid] = m; scv[wid] = cv; }
    __syncthreads();
    if (tid == 0) {
        float mm = smax[0]; int tvc = scv[0];
        #pragma unroll
        for (int i = 1; i < 8; i++) { mm = fmaxf(mm, smax[i]); tvc += scv[i]; }
        g_vblk[blockIdx.x] = tvc;
        atomicAdd(&g_vcount[img], tvc);
        atomicMax(&g_emax_bits[img], __float_as_uint(mm));
    }
}

// ----------------------------------------------------------------------------
// Per-tile e-mask bits + counts (reads g_edge only).
__global__ void k_count() {
    int img = blockIdx.x / NB;
    int tid = threadIdx.x;
    int lane = tid & 31, wid = tid >> 5;
    const unsigned full = 0xffffffffu;

    float thresh = 0.1f * __uint_as_float(g_emax_bits[img]);
    float4 ed = *(const float4*)(g_edge + (size_t)blockIdx.x * 1024 + tid * 4);

    unsigned ne = (unsigned)(ed.x >= thresh)
                | ((unsigned)(ed.y >= thresh) << 1)
                | ((unsigned)(ed.z >= thresh) << 2)
                | ((unsigned)(ed.w >= thresh) << 3);

    unsigned we = ne << (4 * (lane & 7));
    #pragma unroll
    for (int off = 4; off; off >>= 1) we |= __shfl_xor_sync(full, we, off);
    if ((lane & 7) == 0)
        g_emaskw[(size_t)blockIdx.x * 32 + (tid >> 3)] = we;

    int ce = __popc(ne);
    __shared__ int sce[8];
    #pragma unroll
    for (int off = 16; off; off >>= 1) ce += __shfl_down_sync(full, ce, off);
    if (lane == 0) sce[wid] = ce;
    __syncthreads();
    if (tid == 0) {
        int te = 0;
        #pragma unroll
        for (int i = 0; i < 8; i++) te += sce[i];
        g_eblk[blockIdx.x] = te;
        atomicAdd(&g_ecount[img], te);
    }
}

// ----------------------------------------------------------------------------
// Stable scatter from bitmasks, staged through shared memory so all global
// stores are coalesced. Tile offset = inline reduce of preceding tile counts.
// If vcount == P (all-valid), vsel is the identity -> skip all v work.
__global__ void k_scatter() {
    int img = blockIdx.x / NB;
    int b   = blockIdx.x - img * NB;
    int tid = threadIdx.x;
    int lane = tid & 31, wid = tid >> 5;
    const unsigned full = 0xffffffffu;

    bool vall = (g_vcount[img] == P);

    unsigned wordE = g_emaskw[(size_t)blockIdx.x * 32 + (tid >> 3)];
    unsigned ne = (wordE >> (4 * (tid & 7))) & 0xFu;
    unsigned nv = 0;
    if (!vall) {
        unsigned wordV = g_vmaskw[(size_t)blockIdx.x * 32 + (tid >> 3)];
        nv = (wordV >> (4 * (tid & 7))) & 0xFu;
    }
    float4 th4 = *(const float4*)(g_theta + (size_t)blockIdx.x * 1024 + tid * 4);
    float thv[4] = { th4.x, th4.y, th4.z, th4.w };

    int ce = __popc(ne);
    int cv = __popc(nv);

    // per-thread partial sums of preceding tile counts (coalesced)
    int oe = 0, ov = 0;
    for (int t = tid; t < b; t += 256) {
        oe += g_eblk[img * NB + t];
        if (!vall) ov += g_vblk[img * NB + t];
    }

    // warp: inclusive scan of (ce,cv), reduce of (oe,ov)
    int ice = ce, icv = cv;
    #pragma unroll
    for (int off = 1; off < 32; off <<= 1) {
        int a = __shfl_up_sync(full, ice, off);
        int c = __shfl_up_sync(full, icv, off);
        if (lane >= off) { ice += a; icv += c; }
    }
    #pragma unroll
    for (int off = 16; off; off >>= 1) {
        oe += __shfl_down_sync(full, oe, off);
        ov += __shfl_down_sync(full, ov, off);
    }

    __shared__ int wce[8], wcv[8], woe[8], wov[8];
    __shared__ int wbe[8], wbv[8];
    __shared__ int s_offe, s_offv, s_tote, s_totv;
    __shared__ int2 s_e[1024];
    __shared__ int  s_v[1024];
    if (lane == 31) { wce[wid] = ice; wcv[wid] = icv; }
    if (lane == 0)  { woe[wid] = oe;  wov[wid] = ov;  }
    __syncthreads();
    if (tid == 0) {
        int offE = 0, offV = 0;
        #pragma unroll
        for (int i = 0; i < 8; i++) { offE += woe[i]; offV += wov[i]; }
        int accE = 0, accV = 0;
        #pragma unroll
        for (int i = 0; i < 8; i++) {
            wbe[i] = accE; accE += wce[i];
            wbv[i] = accV; accV += wcv[i];
        }
        s_offe = offE; s_offv = offV;
        s_tote = accE; s_totv = accV;
    }
    __syncthreads();

    // compact into shared at stable local ranks
    int le = wbe[wid] + (ice - ce);
    int p0 = b * 1024 + tid * 4;
    #pragma unroll
    for (int j = 0; j < 4; j++)
        if ((ne >> j) & 1u)
            s_e[le++] = make_int2(p0 + j, __float_as_int(thv[j]));
    if (!vall) {
        int lv = wbv[wid] + (icv - cv);
        #pragma unroll
        for (int j = 0; j < 4; j++)
            if ((nv >> j) & 1u)
                s_v[lv++] = p0 + j;
    }
    __syncthreads();

    // coalesced global stores
    size_t imgP = (size_t)img * P;
    int tote = s_tote, offe = s_offe;
    for (int t = tid; t < tote; t += 256)
        g_epack[imgP + offe + t] = s_e[t];
    if (!vall) {
        int totv = s_totv, offv = s_offv;
        for (int t = tid; t < totv; t += 256)
            g_vsel[imgP + offv + t] = s_v[t];
    }
}

// ----------------------------------------------------------------------------
// Main sampling kernel: one thread = TWO samples (262144 threads -> occupancy
// no longer capped by grid size), random phases batched 2-wide (14 independent
// gathers in flight per thread), sequential inputs vectorized. Final loss is
// computed by the last block to finish (ticket), which also resets all state.
#define IPT 2
__global__ void __launch_bounds__(256)
k_sample(const int* __restrict__ ra,
         const int* __restrict__ rd,
         const int* __restrict__ rp,
         float* __restrict__ out) {
    int t = blockIdx.x * blockDim.x + threadIdx.x;   // < NIMG*S/IPT
    float eqf = 0.0f, uqf = 0.0f;

    {
        int img = t / (S / IPT);
        int g   = t - img * (S / IPT);               // sample pair in image
        size_t imgP = (size_t)img * P;
        const float2* pt_i = g_pt + imgP;

        int ec = g_ecount[img];
        int vc = g_vcount[img];

        // ---- phase 0: vectorized sequential inputs ----
        int2 rav = __ldg((const int2*)ra + img * (S / IPT) + g);
        int2 rdv[4];
        #pragma unroll
        for (int j = 0; j < 4; j++)
            rdv[j] = __ldg((const int2*)rd + (img * 4 + j) * (S / IPT) + g);
        int4 rpv = __ldg((const int4*)rp + img * (S / IPT) + g); // 4 perm idx
        int rav_i[IPT] = { rav.x, rav.y };
        int rpA[IPT]   = { rpv.x, rpv.z };
        int rpB[IPT]   = { rpv.y, rpv.w };

        // ---- phase 1: independent anchor gathers ----
        int2 ap[IPT];
        if (ec > 0) {
            #pragma unroll
            for (int i = 0; i < IPT; i++)
                ap[i] = __ldg(g_epack + imgP + (rav_i[i] % ec));
        } else {
            int2 z = make_int2(0, __float_as_int(g_theta[imgP]));
            #pragma unroll
            for (int i = 0; i < IPT; i++) ap[i] = z;
        }

        // ---- phase 2: trig + index computation ----
        int q[IPT][6];
        #pragma unroll
        for (int i = 0; i < IPT; i++) {
            float th = __int_as_float(ap[i].y);
            float ct, st;
            sincosf(th, &st, &ct);
            int row_a = ap[i].x / W;
            int col_a = ap[i].x - row_a * W;
            int rdj[4] = { (&rdv[0].x)[i], (&rdv[1].x)[i], (&rdv[2].x)[i], (&rdv[3].x)[i] };
            #pragma unroll
            for (int j = 0; j < 4; j++) {
                float sign = (j < 2) ? -1.0f : 1.0f;
                float d    = ((float)rdj[j] + 2.0f) * sign;
                int cc = col_a + (int)rintf(d * ct);   // jnp.round = half-to-even
                int rr = row_a + (int)rintf(d * st);
                cc = min(max(cc, 0), W - 1);
                rr = min(max(rr, 0), H - 1);
                q[i][j] = rr * W + cc;
            }
        }
        if (vc == P) {                 // all-valid: vsel is identity
            #pragma unroll
            for (int i = 0; i < IPT; i++) {
                q[i][4] = rpA[i] % vc;
                q[i][5] = rpB[i] % vc;
            }
        } else if (vc > 0) {
            #pragma unroll
            for (int i = 0; i < IPT; i++) {
                q[i][4] = __ldg(g_vsel + imgP + (rpA[i] % vc));
                q[i][5] = __ldg(g_vsel + imgP + (rpB[i] % vc));
            }
        } else {
            #pragma unroll
            for (int i = 0; i < IPT; i++) { q[i][4] = 0; q[i][5] = 0; }
        }

        // ---- phase 3: 12 independent packed gathers ----
        float2 pv[IPT][6];
        #pragma unroll
        for (int i = 0; i < IPT; i++)
            #pragma unroll
            for (int j = 0; j < 6; j++)
                pv[i][j] = __ldg(pt_i + q[i][j]);

        // ---- phase 4: pair math ----
        const int PA[4] = {0, 1, 2, 4};
        const int PB[4] = {1, 2, 3, 5};
        const float hi = 1.0f + 0.03f;             // 1 + SIGMA in f32
        const float lo = (float)(1.0 / 1.03);      // double-computed like Python

        #pragma unroll
        for (int i = 0; i < IPT; i++) {
            #pragma unroll
            for (int k = 0; k < 4; k++) {
                float iA = pv[i][PA[k]].x, iB = pv[i][PB[k]].x;
                float tA = pv[i][PA[k]].y, tB = pv[i][PB[k]].y;

                float cm = ((tA > MASK_VALUE) && (tB > MASK_VALUE)) ? 1.0f : 0.0f;
                float ratio = (tA + 1e-6f) / (tB + 1e-6f);
                bool  meq = (ratio < hi) && (ratio > lo);

                if (meq) {
                    float dd = iA - iB;
                    eqf += dd * dd * cm;
                } else {
                    float lbl = (ratio >= hi) ? 1.0f : -1.0f;
                    uqf += log1pf(expf((iB - iA) * lbl)) * cm;
                }
            }
        }
    }

    // block reduce (promote to double) -> single atomicAdd pair per block
    double eq = (double)eqf, uq = (double)uqf;
    #pragma unroll
    for (int off = 16; off; off >>= 1) {
        eq += __shfl_down_sync(0xffffffffu, eq, off);
        uq += __shfl_down_sync(0xffffffffu, uq, off);
    }
    __shared__ double sh_eq[8];
    __shared__ double sh_uq[8];
    int lane = threadIdx.x & 31, wid = threadIdx.x >> 5;
    if (lane == 0) { sh_eq[wid] = eq; sh_uq[wid] = uq; }
    __syncthreads();
    if (wid == 0 && lane == 0) {
        eq = 0.0; uq = 0.0;
        #pragma unroll
        for (int i = 0; i < 8; i++) { eq += sh_eq[i]; uq += sh_uq[i]; }
        atomicAdd(&g_acc_eq, eq);
        atomicAdd(&g_acc_uq, uq);
    }

    // ---- fused finalization: last block computes the loss + resets state ---
    __shared__ bool is_last;
    __threadfence();
    if (threadIdx.x == 0) {
        unsigned tk = atomicAdd(&g_ticket, 1u);
        is_last = (tk == gridDim.x - 1);
    }
    __syncthreads();
    if (is_last) {
        if (threadIdx.x == 0) {
            double eqv = atomicAdd(&g_acc_eq, 0.0);
            double uqv = atomicAdd(&g_acc_uq, 0.0);
            double denom = 4.0 * (double)S;               // pairs per image
            double loss  = (eqv + uqv) / denom / (double)NIMG;
            out[0] = (float)loss;
            g_acc_eq = 0.0;
            g_acc_uq = 0.0;
            g_ticket = 0u;
        }
        if (threadIdx.x < NIMG) {
            g_emax_bits[threadIdx.x] = 0u;
            g_ecount[threadIdx.x] = 0;
            g_vcount[threadIdx.x] = 0;
        }
    }
}

// ----------------------------------------------------------------------------
extern "C" void kernel_launch(void* const* d_in, const int* in_sizes, int n_in,
                              void* d_out, int out_size) {
    (void)in_sizes; (void)n_in; (void)out_size;

    const float* inputs  = (const float*)d_in[0];
    const float* targets = (const float*)d_in[1];
    const float* images  = (const float*)d_in[2];
    const int*   ra      = (const int*)d_in[3];
    const int*   rd      = (const int*)d_in[4];
    const int*   rp      = (const int*)d_in[5];
    float*       out     = (float*)d_out;

    k_sobel  <<<NIMG * NB, 256>>>(images, inputs, targets);
    k_count  <<<NIMG * NB, 256>>>();
    k_scatter<<<NIMG * NB, 256>>>();
    k_sample <<<(NIMG * S / IPT) / 256, 256>>>(ra, rd, rp, out);
}

// round 17
// speedup vs baseline: 1.2894x; 1.0083x over previous
#include <cuda_runtime.h>
#include <math.h>

// ---------------------------------------------------------------------------
// GemoLoss — GB300. n=4, h=768, w=1024, S=131072.
// R15: champion prep (R10) + k_sample IPT=4 (proven best, R12) + ticket-fused
//      finalization (R14) + early-issued rp-gathers (overlap with anchor trip).
// ---------------------------------------------------------------------------

#define NIMG 4
#define H    768
#define W    1024
#define P    (H * W)          // 786432
#define S    131072
#define NB   (P / 1024)       // 768 tiles of 1024 pixels per image

#define MASK_VALUE (-1e-8f)

// ------------- device scratch (zero-initialized at module load) -------------
__device__ float    g_edge [NIMG * P];
__device__ float    g_theta[NIMG * P];
__device__ float2   g_pt   [NIMG * P];        // packed (inp, tgt) per pixel
__device__ int2     g_epack[NIMG * P];        // packed (pixel, theta_bits)
__device__ int      g_vsel [NIMG * P];        // stable select for valid mask
__device__ unsigned g_emaskw[NIMG * NB * 32]; // 1024-bit tile masks
__device__ unsigned g_vmaskw[NIMG * NB * 32];
__device__ unsigned g_emax_bits[NIMG];        // edge max as float bits
__device__ int      g_eblk[NIMG * NB];        // per-tile mask counts
__device__ int      g_vblk[NIMG * NB];
__device__ int      g_ecount[NIMG];
__device__ int      g_vcount[NIMG];
__device__ unsigned g_ticket;                 // last-block detection
__device__ double   g_acc_eq;
__device__ double   g_acc_uq;

// ----------------------------------------------------------------------------
// Sobel on channel 0 (cross-correlation). One block == one 1024-px tile,
// 4 consecutive pixels per thread. Border pixels get edge=0, theta=0.
// Fused: per-image edge max, (inp,tgt) packing, v-mask bits/counts.
__global__ void k_sobel(const float* __restrict__ images,
                        const float* __restrict__ inp,
                        const float* __restrict__ tgt) {
    int gid = blockIdx.x * blockDim.x + threadIdx.x;   // < NIMG*P/4
    int img = gid / (P / 4);
    int t   = gid - img * (P / 4);
    int p0  = t * 4;                                   // 4 px, same row (W%4==0)
    int y   = p0 / W;
    int x0  = p0 - y * W;
    int tid = threadIdx.x;
    int lane = tid & 31, wid = tid >> 5;
    const unsigned full = 0xffffffffu;

    // pack (inp,tgt) and build v-mask nibble from the same tgt load
    float4 tv = __ldg((const float4*)(tgt) + gid);
    {
        float4 iv = __ldg((const float4*)(inp) + gid);
        float4* pt4 = (float4*)g_pt;
        pt4[gid * 2    ] = make_float4(iv.x, tv.x, iv.y, tv.y);
        pt4[gid * 2 + 1] = make_float4(iv.z, tv.z, iv.w, tv.w);
    }
    unsigned nv = (unsigned)(tv.x > MASK_VALUE)
                | ((unsigned)(tv.y > MASK_VALUE) << 1)
                | ((unsigned)(tv.z > MASK_VALUE) << 2)
                | ((unsigned)(tv.w > MASK_VALUE) << 3);

    float e[4]  = {0.f, 0.f, 0.f, 0.f};
    float th[4] = {0.f, 0.f, 0.f, 0.f};
    if (y > 0 && y < H - 1) {
        const float* I = images + (size_t)img * 3 * P;
        float r0[6], r1[6], r2[6];
        float4 a0 = __ldg((const float4*)(I + (y - 1) * W + x0));
        float4 a1 = __ldg((const float4*)(I + (y    ) * W + x0));
        float4 a2 = __ldg((const float4*)(I + (y + 1) * W + x0));
        r0[1]=a0.x; r0[2]=a0.y; r0[3]=a0.z; r0[4]=a0.w;
        r1[1]=a1.x; r1[2]=a1.y; r1[3]=a1.z; r1[4]=a1.w;
        r2[1]=a2.x; r2[2]=a2.y; r2[3]=a2.z; r2[4]=a2.w;
        if (x0 > 0) {
            r0[0] = __ldg(I + (y - 1) * W + x0 - 1);
            r1[0] = __ldg(I + (y    ) * W + x0 - 1);
            r2[0] = __ldg(I + (y + 1) * W + x0 - 1);
        } else { r0[0] = r1[0] = r2[0] = 0.f; }
        if (x0 + 4 < W) {
            r0[5] = __ldg(I + (y - 1) * W + x0 + 4);
            r1[5] = __ldg(I + (y    ) * W + x0 + 4);
            r2[5] = __ldg(I + (y + 1) * W + x0 + 4);
        } else { r0[5] = r1[5] = r2[5] = 0.f; }

        #pragma unroll
        for (int j = 0; j < 4; j++) {
            int x = x0 + j;
            if (x > 0 && x < W - 1) {
                float a  = r0[j], b = r0[j + 1], c = r0[j + 2];
                float d  = r1[j],                f = r1[j + 2];
                float g  = r2[j], hh = r2[j + 1], i = r2[j + 2];
                // kx = [[-1,0,1],[-2,0,2],[-1,0,1]], ky = [[1,2,1],[0,0,0],[-1,-2,-1]]
                float gx = -a;  gx += c;  gx += -2.0f * d;  gx += 2.0f * f;  gx += -g;  gx += i;
                float gy =  a;  gy += 2.0f * b;  gy += c;  gy += -g;  gy += -2.0f * hh; gy += -i;
                e[j]  = sqrtf(gx * gx + gy * gy);
                th[j] = atan2f(gy, gx);
            }
        }
    }
    *(float4*)(g_edge  + (size_t)gid * 4) = make_float4(e[0],  e[1],  e[2],  e[3]);
    *(float4*)(g_theta + (size_t)gid * 4) = make_float4(th[0], th[1], th[2], th[3]);

    // v-mask word assembly (8 lanes * 4 bits) + tile count
    unsigned wv = nv << (4 * (lane & 7));
    #pragma unroll
    for (int off = 4; off; off >>= 1) wv |= __shfl_xor_sync(full, wv, off);
    if ((lane & 7) == 0)
        g_vmaskw[(size_t)blockIdx.x * 32 + (tid >> 3)] = wv;

    // block reductions: edge max + v count
    __shared__ float smax[8];
    __shared__ int   scv[8];
    float m = fmaxf(fmaxf(e[0], e[1]), fmaxf(e[2], e[3]));
    int cv = __popc(nv);
    #pragma unroll
    for (int off = 16; off; off >>= 1) {
        m  = fmaxf(m, __shfl_down_sync(full, m, off));
        cv += __shfl_down_sync(full, cv, off);
    }
    if (lane == 0) { smax[wid] = m; scv[wid] = cv; }
    __syncthreads();
    if (tid == 0) {
        float mm = smax[0]; int tvc = scv[0];
        #pragma unroll
        for (int i = 1; i < 8; i++) { mm = fmaxf(mm, smax[i]); tvc += scv[i]; }
        g_vblk[blockIdx.x] = tvc;
        atomicAdd(&g_vcount[img], tvc);
        atomicMax(&g_emax_bits[img], __float_as_uint(mm));
    }
}

// ----------------------------------------------------------------------------
// Per-tile e-mask bits + counts (reads g_edge only).
__global__ void k_count() {
    int img = blockIdx.x / NB;
    int tid = threadIdx.x;
    int lane = tid & 31, wid = tid >> 5;
    const unsigned full = 0xffffffffu;

    float thresh = 0.1f * __uint_as_float(g_emax_bits[img]);
    float4 ed = *(const float4*)(g_edge + (size_t)blockIdx.x * 1024 + tid * 4);

    unsigned ne = (unsigned)(ed.x >= thresh)
                | ((unsigned)(ed.y >= thresh) << 1)
                | ((unsigned)(ed.z >= thresh) << 2)
                | ((unsigned)(ed.w >= thresh) << 3);

    unsigned we = ne << (4 * (lane & 7));
    #pragma unroll
    for (int off = 4; off; off >>= 1) we |= __shfl_xor_sync(full, we, off);
    if ((lane & 7) == 0)
        g_emaskw[(size_t)blockIdx.x * 32 + (tid >> 3)] = we;

    int ce = __popc(ne);
    __shared__ int sce[8];
    #pragma unroll
    for (int off = 16; off; off >>= 1) ce += __shfl_down_sync(full, ce, off);
    if (lane == 0) sce[wid] = ce;
    __syncthreads();
    if (tid == 0) {
        int te = 0;
        #pragma unroll
        for (int i = 0; i < 8; i++) te += sce[i];
        g_eblk[blockIdx.x] = te;
        atomicAdd(&g_ecount[img], te);
    }
}

// ----------------------------------------------------------------------------
// Stable scatter from bitmasks, staged through shared memory so all global
// stores are coalesced. Tile offset = inline reduce of preceding tile counts.
// If vcount == P (all-valid), vsel is the identity -> skip all v work.
__global__ void k_scatter() {
    int img = blockIdx.x / NB;
    int b   = blockIdx.x - img * NB;
    int tid = threadIdx.x;
    int lane = tid & 31, wid = tid >> 5;
    const unsigned full = 0xffffffffu;

    bool vall = (g_vcount[img] == P);

    unsigned wordE = g_emaskw[(size_t)blockIdx.x * 32 + (tid >> 3)];
    unsigned ne = (wordE >> (4 * (tid & 7))) & 0xFu;
    unsigned nv = 0;
    if (!vall) {
        unsigned wordV = g_vmaskw[(size_t)blockIdx.x * 32 + (tid >> 3)];
        nv = (wordV >> (4 * (tid & 7))) & 0xFu;
    }
    float4 th4 = *(const float4*)(g_theta + (size_t)blockIdx.x * 1024 + tid * 4);
    float thv[4] = { th4.x, th4.y, th4.z, th4.w };

    int ce = __popc(ne);
    int cv = __popc(nv);

    // per-thread partial sums of preceding tile counts (coalesced)
    int oe = 0, ov = 0;
    for (int t = tid; t < b; t += 256) {
        oe += g_eblk[img * NB + t];
        if (!vall) ov += g_vblk[img * NB + t];
    }

    // warp: inclusive scan of (ce,cv), reduce of (oe,ov)
    int ice = ce, icv = cv;
    #pragma unroll
    for (int off = 1; off < 32; off <<= 1) {
        int a = __shfl_up_sync(full, ice, off);
        int c = __shfl_up_sync(full, icv, off);
        if (lane >= off) { ice += a; icv += c; }
    }
    #pragma unroll
    for (int off = 16; off; off >>= 1) {
        oe += __shfl_down_sync(full, oe, off);
        ov += __shfl_down_sync(full, ov, off);
    }

    __shared__ int wce[8], wcv[8], woe[8], wov[8];
    __shared__ int wbe[8], wbv[8];
    __shared__ int s_offe, s_offv, s_tote, s_totv;
    __shared__ int2 s_e[1024];
    __shared__ int  s_v[1024];
    if (lane == 31) { wce[wid] = ice; wcv[wid] = icv; }
    if (lane == 0)  { woe[wid] = oe;  wov[wid] = ov;  }
    __syncthreads();
    if (tid == 0) {
        int offE = 0, offV = 0;
        #pragma unroll
        for (int i = 0; i < 8; i++) { offE += woe[i]; offV += wov[i]; }
        int accE = 0, accV = 0;
        #pragma unroll
        for (int i = 0; i < 8; i++) {
            wbe[i] = accE; accE += wce[i];
            wbv[i] = accV; accV += wcv[i];
        }
        s_offe = offE; s_offv = offV;
        s_tote = accE; s_totv = accV;
    }
    __syncthreads();

    // compact into shared at stable local ranks
    int le = wbe[wid] + (ice - ce);
    int p0 = b * 1024 + tid * 4;
    #pragma unroll
    for (int j = 0; j < 4; j++)
        if ((ne >> j) & 1u)
            s_e[le++] = make_int2(p0 + j, __float_as_int(thv[j]));
    if (!vall) {
        int lv = wbv[wid] + (icv - cv);
        #pragma unroll
        for (int j = 0; j < 4; j++)
            if ((nv >> j) & 1u)
                s_v[lv++] = p0 + j;
    }
    __syncthreads();

    // coalesced global stores
    size_t imgP = (size_t)img * P;
    int tote = s_tote, offe = s_offe;
    for (int t = tid; t < tote; t += 256)
        g_epack[imgP + offe + t] = s_e[t];
    if (!vall) {
        int totv = s_totv, offv = s_offv;
        for (int t = tid; t < totv; t += 256)
            g_vsel[imgP + offv + t] = s_v[t];
    }
}

// ----------------------------------------------------------------------------
// Main sampling kernel: one thread = FOUR samples (proven-best ILP config).
// The rp-derived gathers (q4/q5) are independent of the anchor chain and are
// issued FIRST so they overlap the epack L2 round-trip. Last block (ticket)
// computes the final loss and resets all state.
#define IPT 4
__global__ void __launch_bounds__(128)
k_sample(const int* __restrict__ ra,
         const int* __restrict__ rd,
         const int* __restrict__ rp,
         float* __restrict__ out) {
    int t = blockIdx.x * blockDim.x + threadIdx.x;   // < NIMG*S/IPT
    float eqf = 0.0f, uqf = 0.0f;

    {
        int img = t / (S / IPT);
        int g   = t - img * (S / IPT);               // sample group in image
        size_t imgP = (size_t)img * P;
        const float2* pt_i = g_pt + imgP;

        int ec = g_ecount[img];
        int vc = g_vcount[img];

        // ---- phase 0: vectorized sequential inputs ----
        int4 rav  = __ldg((const int4*)ra + img * (S / IPT) + g);
        int4 rdv[4];
        #pragma unroll
        for (int j = 0; j < 4; j++)
            rdv[j] = __ldg((const int4*)rd + (img * 4 + j) * (S / IPT) + g);
        int4 rpa = __ldg((const int4*)rp + img * (S / 2) + 2 * g);      // s0,s1
        int4 rpb = __ldg((const int4*)rp + img * (S / 2) + 2 * g + 1);  // s2,s3
        int rav_i[IPT] = { rav.x, rav.y, rav.z, rav.w };
        int rpA[IPT]   = { rpa.x, rpa.z, rpb.x, rpb.z };
        int rpB[IPT]   = { rpa.y, rpa.w, rpb.y, rpb.w };

        // ---- phase 1a: anchor-independent endpoint indices + gathers -------
        // q4/q5 depend only on rp/vc -> their pt loads fly concurrently with
        // the epack anchor loads below (removes one serial L2 trip).
        int q4[IPT], q5[IPT];
        if (vc == P) {                 // all-valid: vsel is identity
            #pragma unroll
            for (int i = 0; i < IPT; i++) {
                q4[i] = rpA[i] % vc;
                q5[i] = rpB[i] % vc;
            }
        } else if (vc > 0) {
            #pragma unroll
            for (int i = 0; i < IPT; i++) {
                q4[i] = __ldg(g_vsel + imgP + (rpA[i] % vc));
                q5[i] = __ldg(g_vsel + imgP + (rpB[i] % vc));
            }
        } else {
            #pragma unroll
            for (int i = 0; i < IPT; i++) { q4[i] = 0; q5[i] = 0; }
        }
        float2 pv4[IPT], pv5[IPT];
        #pragma unroll
        for (int i = 0; i < IPT; i++) pv4[i] = __ldg(pt_i + q4[i]);
        #pragma unroll
        for (int i = 0; i < IPT; i++) pv5[i] = __ldg(pt_i + q5[i]);

        // ---- phase 1b: 4 independent anchor gathers ----
        int2 ap[IPT];
        if (ec > 0) {
            #pragma unroll
            for (int i = 0; i < IPT; i++)
                ap[i] = __ldg(g_epack + imgP + (rav_i[i] % ec));
        } else {
            int2 z = make_int2(0, __float_as_int(g_theta[imgP]));
            #pragma unroll
            for (int i = 0; i < IPT; i++) ap[i] = z;
        }

        // ---- phase 2: trig + anchor-relative indices ----
        int q[IPT][4];
        #pragma unroll
        for (int i = 0; i < IPT; i++) {
            float th = __int_as_float(ap[i].y);
            float ct, st;
            sincosf(th, &st, &ct);
            int row_a = ap[i].x / W;
            int col_a = ap[i].x - row_a * W;
            int rdj[4] = { (&rdv[0].x)[i], (&rdv[1].x)[i], (&rdv[2].x)[i], (&rdv[3].x)[i] };
            #pragma unroll
            for (int j = 0; j < 4; j++) {
                float sign = (j < 2) ? -1.0f : 1.0f;
                float d    = ((float)rdj[j] + 2.0f) * sign;
                int cc = col_a + (int)rintf(d * ct);   // jnp.round = half-to-even
                int rr = row_a + (int)rintf(d * st);
                cc = min(max(cc, 0), W - 1);
                rr = min(max(rr, 0), H - 1);
                q[i][j] = rr * W + cc;
            }
        }

        // ---- phase 3: 16 independent anchor-chain gathers ----
        float2 pv[IPT][4];
        #pragma unroll
        for (int i = 0; i < IPT; i++)
            #pragma unroll
            for (int j = 0; j < 4; j++)
                pv[i][j] = __ldg(pt_i + q[i][j]);

        // ---- phase 4: pair math ----
        const float hi = 1.0f + 0.03f;             // 1 + SIGMA in f32
        const float lo = (float)(1.0 / 1.03);      // double-computed like Python

        #pragma unroll
        for (int i = 0; i < IPT; i++) {
            float2 eA[4] = { pv[i][0], pv[i][1], pv[i][2], pv4[i] };
            float2 eB[4] = { pv[i][1], pv[i][2], pv[i][3], pv5[i] };
            #pragma unroll
            for (int k = 0; k < 4; k++) {
                float iA = eA[k].x, iB = eB[k].x;
                float tA = eA[k].y, tB = eB[k].y;

                float cm = ((tA > MASK_VALUE) && (tB > MASK_VALUE)) ? 1.0f : 0.0f;
                float ratio = (tA + 1e-6f) / (tB + 1e-6f);
                bool  meq = (ratio < hi) && (ratio > lo);

                if (meq) {
                    float dd = iA - iB;
                    eqf += dd * dd * cm;
                } else {
                    float lbl = (ratio >= hi) ? 1.0f : -1.0f;
                    uqf += log1pf(expf((iB - iA) * lbl)) * cm;
                }
            }
        }
    }

    // block reduce (promote to double) -> single atomicAdd pair per block
    double eq = (double)eqf, uq = (double)uqf;
    #pragma unroll
    for (int off = 16; off; off >>= 1) {
        eq += __shfl_down_sync(0xffffffffu, eq, off);
        uq += __shfl_down_sync(0xffffffffu, uq, off);
    }
    __shared__ double sh_eq[4];
    __shared__ double sh_uq[4];
    int lane = threadIdx.x & 31, wid = threadIdx.x >> 5;
    if (lane == 0) { sh_eq[wid] = eq; sh_uq[wid] = uq; }
    __syncthreads();
    if (wid == 0 && lane == 0) {
        eq = sh_eq[0] + sh_eq[1] + sh_eq[2] + sh_eq[3];
        uq = sh_uq[0] + sh_uq[1] + sh_uq[2] + sh_uq[3];
        atomicAdd(&g_acc_eq, eq);
        atomicAdd(&g_acc_uq, uq);
    }

    // ---- fused finalization: last block computes the loss + resets state ---
    __shared__ bool is_last;
    __threadfence();
    if (threadIdx.x == 0) {
        unsigned tk = atomicAdd(&g_ticket, 1u);
        is_last = (tk == gridDim.x - 1);
    }
    __syncthreads();
    if (is_last) {
        if (threadIdx.x == 0) {
            double eqv = atomicAdd(&g_acc_eq, 0.0);
            double uqv = atomicAdd(&g_acc_uq, 0.0);
            double denom = 4.0 * (double)S;               // pairs per image
            double loss  = (eqv + uqv) / denom / (double)NIMG;
            out[0] = (float)loss;
            g_acc_eq = 0.0;
            g_acc_uq = 0.0;
            g_ticket = 0u;
        }
        if (threadIdx.x < NIMG) {
            g_emax_bits[threadIdx.x] = 0u;
            g_ecount[threadIdx.x] = 0;
            g_vcount[threadIdx.x] = 0;
        }
    }
}

// ----------------------------------------------------------------------------
extern "C" void kernel_launch(void* const* d_in, const int* in_sizes, int n_in,
                              void* d_out, int out_size) {
    (void)in_sizes; (void)n_in; (void)out_size;

    const float* inputs  = (const float*)d_in[0];
    const float* targets = (const float*)d_in[1];
    const float* images  = (const float*)d_in[2];
    const int*   ra      = (const int*)d_in[3];
    const int*   rd      = (const int*)d_in[4];
    const int*   rp      = (const int*)d_in[5];
    float*       out     = (float*)d_out;

    k_sobel  <<<NIMG * NB, 256>>>(images, inputs, targets);
    k_count  <<<NIMG * NB, 256>>>();
    k_scatter<<<NIMG * NB, 256>>>();
    k_sample <<<(NIMG * S / IPT) / 128, 128>>>(ra, rd, rp, out);
}